// round 17
// baseline (speedup 1.0000x reference)
#include <cuda_runtime.h>
#include <cuda_bf16.h>
#include <math.h>
#include <cstdint>

#define BB 2
#define SS 2048
#define SA 2051            // S + 3 physics tokens
#define HID 1024
#define NH 16
#define HD 64
#define STREAM (BB*SA*HID) // elems per stream
#define MTOT2 (2*BB*SA)    // 8204 merged rows
#define WSZ (HID*HID)

#define SWZ(o) ((o) ^ (((o) >> 3) & 0x70))

// ---------------- GEMM tiling (256 thr, warp 64x64, CTA 128x256, KC=128, 2-stage) ----
#define TM 128
#define TN3 256
#define KC7 128
#define NCH7 (HID/KC7)     // 8
#define A_STR7 272         // 256B data + 16 pad
#define B_STR3 528         // 512B data + 16 pad
#define SA7 0
#define SB7 (128*A_STR7)               // 34816
#define STG7 (SB7 + 128*B_STR3)        // 102400
#define GEMM7_SMEM (2*STG7)            // 204800

// ---------------- attention smem (hi-only, 9-slot / 3-group ring) ----------------
#define AT_KH 0
#define AT_VH 8192
#define AT_STG 16384
#define ATTN11_SMEM (9*AT_STG)         // 147456

// ---------------- device scratch ----------------
__device__ float g_proj[2*STREAM];           // out-proj fp32 result
__device__ __nv_bfloat16 g_augH[2*STREAM];
__device__ __nv_bfloat16 g_QH[2*STREAM];     // pre-scaled by 0.125*log2(e)
__device__ __nv_bfloat16 g_KH[2*STREAM];
__device__ __nv_bfloat16 g_VH[2*STREAM];
__device__ __nv_bfloat16 g_attH[2*STREAM];
__device__ __nv_bfloat16 g_WH[4*WSZ];

// ---------------- helpers ----------------
__device__ __forceinline__ uint32_t smem_u32(const void* p) {
    uint32_t a;
    asm("{ .reg .u64 t; cvta.to.shared.u64 t, %1; cvt.u32.u64 %0, t; }" : "=r"(a) : "l"(p));
    return a;
}
__device__ __forceinline__ void mma16816(float* d, const uint32_t* a, const uint32_t* b) {
    asm volatile(
        "mma.sync.aligned.m16n8k16.row.col.f32.bf16.bf16.f32 "
        "{%0,%1,%2,%3}, {%4,%5,%6,%7}, {%8,%9}, {%0,%1,%2,%3};"
        : "+f"(d[0]), "+f"(d[1]), "+f"(d[2]), "+f"(d[3])
        : "r"(a[0]), "r"(a[1]), "r"(a[2]), "r"(a[3]), "r"(b[0]), "r"(b[1]));
}
__device__ __forceinline__ void ldmx4(uint32_t* r, uint32_t addr) {
    asm volatile("ldmatrix.sync.aligned.m8n8.x4.shared.b16 {%0,%1,%2,%3}, [%4];"
                 : "=r"(r[0]), "=r"(r[1]), "=r"(r[2]), "=r"(r[3]) : "r"(addr));
}
__device__ __forceinline__ void ldmx4t(uint32_t* r, uint32_t addr) {
    asm volatile("ldmatrix.sync.aligned.m8n8.x4.trans.shared.b16 {%0,%1,%2,%3}, [%4];"
                 : "=r"(r[0]), "=r"(r[1]), "=r"(r[2]), "=r"(r[3]) : "r"(addr));
}
__device__ __forceinline__ void cpasync16(uint32_t dst, const void* src, int sz) {
    asm volatile("cp.async.cg.shared.global [%0], [%1], 16, %2;"
                 :: "r"(dst), "l"(src), "r"(sz));
}
__device__ __forceinline__ void cpcommit() { asm volatile("cp.async.commit_group;" ::: "memory"); }
template<int N> __device__ __forceinline__ void cpwait() {
    asm volatile("cp.async.wait_group %0;" :: "n"(N) : "memory");
}
__device__ __forceinline__ uint32_t pk_bf2(__nv_bfloat16 a, __nv_bfloat16 b) {
    __nv_bfloat162 t(a, b);
    return *reinterpret_cast<uint32_t*>(&t);
}
__device__ __forceinline__ uint4 round8(float4 v0, float4 v1) {
    return make_uint4(pk_bf2(__float2bfloat16(v0.x), __float2bfloat16(v0.y)),
                      pk_bf2(__float2bfloat16(v0.z), __float2bfloat16(v0.w)),
                      pk_bf2(__float2bfloat16(v1.x), __float2bfloat16(v1.y)),
                      pk_bf2(__float2bfloat16(v1.z), __float2bfloat16(v1.w)));
}
__device__ __forceinline__ uint32_t cvt_bf2(float lo, float hi) {
    uint32_t r;
    asm("cvt.rn.bf16x2.f32 %0, %1, %2;" : "=r"(r) : "f"(hi), "f"(lo));
    return r;
}
__device__ __forceinline__ uint32_t ex2_bf2(uint32_t x) {
    uint32_t r;
    asm("ex2.approx.ftz.bf16x2 %0, %1;" : "=r"(r) : "r"(x));
    return r;
}

// ---------------- merged prep: build aug (bf16) + round weights ----------------
#define AUG_ITEMS (BB*SA*HID/8)
#define W_ITEMS   (WSZ/8)              // 131072 (= 1<<17)

__global__ void prep_kernel(const float* __restrict__ cnn, const float* __restrict__ llm,
                            const float* __restrict__ energy, const float* __restrict__ mass,
                            const float* __restrict__ momentum,
                            const float* __restrict__ W0, const float* __restrict__ W1,
                            const float* __restrict__ W2, const float* __restrict__ W3) {
    int idx = blockIdx.x * blockDim.x + threadIdx.x;
    if (idx < AUG_ITEMS) {
        int h8  = idx % (HID / 8);
        int row = idx / (HID / 8);
        int s   = row % SA;
        int b   = row / SA;
        float4 c0, c1, l0, l1;
        if (s < SS) {
            const float* cp = cnn + ((size_t)(b * SS + s) * HID) + h8 * 8;
            const float* lp = llm + ((size_t)(b * SS + s) * HID) + h8 * 8;
            c0 = *(const float4*)cp; c1 = *(const float4*)(cp + 4);
            l0 = *(const float4*)lp; l1 = *(const float4*)(lp + 4);
        } else {
            const float* e = (s == SS) ? energy : ((s == SS + 1) ? mass : momentum);
            c0 = *(const float4*)(e + h8 * 8); c1 = *(const float4*)(e + h8 * 8 + 4);
            l0 = c0; l1 = c1;
        }
        size_t o = (size_t)idx * 8;
        *(uint4*)&g_augH[o] = round8(c0, c1);
        *(uint4*)&g_augH[STREAM + o] = round8(l0, l1);
    } else {
        int j = idx - AUG_ITEMS;
        if (j >= 4 * W_ITEMS) return;
        int w = j >> 17;
        int i = j & (W_ITEMS - 1);
        const float* src = (w == 0) ? W0 : (w == 1) ? W1 : (w == 2) ? W2 : W3;
        const float* p = src + (size_t)i * 8;
        float4 v0 = *(const float4*)p, v1 = *(const float4*)(p + 4);
        *(uint4*)&g_WH[(size_t)w * WSZ + (size_t)i * 8] = round8(v0, v1);
    }
}

// ---------------- GEMM v7: KC=128, 2-stage, post-sync loads (8 syncs total) ------
__device__ __forceinline__ void gemm7_load_stage(
    uint32_t sb, int stg, int ch, int tid,
    const __nv_bfloat16* AH, const __nv_bfloat16* WH,
    int row0, int col0, int M) {
    uint32_t base = sb + stg * STG7;
    // A tile: 128 rows x 16 16B-chunks
#pragma unroll
    for (int i = 0; i < 8; i++) {
        int c = tid + i * 256;
        int row = c >> 4, col = c & 15;
        int gr = row0 + row;
        int sz = (gr < M) ? 16 : 0;
        size_t so = (size_t)(sz ? gr : 0) * HID + ch * KC7 + col * 8;
        cpasync16(base + SA7 + row * A_STR7 + col * 16, AH + so, sz);
    }
    // B tile: 128 k-rows x 32 16B-chunks
#pragma unroll
    for (int i = 0; i < 16; i++) {
        int c = tid + i * 256;
        int row = c >> 5, col = c & 31;
        size_t so = (size_t)(ch * KC7 + row) * HID + col0 + col * 8;
        cpasync16(base + SB7 + row * B_STR3 + col * 16, WH + so, 16);
    }
}

__device__ __forceinline__ void gemm7_core(
    const __nv_bfloat16* __restrict__ AH, const __nv_bfloat16* __restrict__ WH,
    const float* __restrict__ bias, float* __restrict__ Cf,
    __nv_bfloat16* __restrict__ CH, float oscale, int M) {
    extern __shared__ char smc[];
    const uint32_t sb = smem_u32(smc);
    const int tid = threadIdx.x, lane = tid & 31, wid = tid >> 5;
    const int wm = wid >> 2, wn = wid & 3;
    const int row0 = blockIdx.y * TM, col0 = blockIdx.x * TN3;

    float acc[4][8][4];
#pragma unroll
    for (int i = 0; i < 4; i++)
#pragma unroll
        for (int j = 0; j < 8; j++)
#pragma unroll
            for (int k = 0; k < 4; k++) acc[i][j][k] = 0.f;

    const uint32_t a_lane = (uint32_t)((lane & 15) * A_STR7 + (lane >> 4) * 16);
    const uint32_t b_lane = (uint32_t)(((((lane >> 3) & 1) * 8) + (lane & 7)) * B_STR3
                                       + (lane >> 4) * 16);

    gemm7_load_stage(sb, 0, 0, tid, AH, WH, row0, col0, M);
    cpcommit();

    for (int ch = 0; ch < NCH7; ch++) {
        cpwait<0>();       // outstanding at this point: exactly stage ch
        __syncthreads();
        // post-sync load: the other slot's prior reads are ordered by the sync above
        if (ch + 1 < NCH7) {
            gemm7_load_stage(sb, (ch + 1) & 1, ch + 1, tid, AH, WH, row0, col0, M);
            cpcommit();
        }

        const uint32_t stg = sb + (ch & 1) * STG7;
#pragma unroll
        for (int ks = 0; ks < 8; ks++) {
            uint32_t bh[8][2];
            const uint32_t bo = stg + SB7 + (uint32_t)(ks * 16 * B_STR3 + wn * 128) + b_lane;
#pragma unroll
            for (int g = 0; g < 4; g++) {
                uint32_t t[4];
                ldmx4t(t, bo + g * 32);
                bh[2*g][0] = t[0]; bh[2*g][1] = t[1];
                bh[2*g+1][0] = t[2]; bh[2*g+1][1] = t[3];
            }
#pragma unroll
            for (int mt = 0; mt < 4; mt++) {
                uint32_t ah[4];
                ldmx4(ah, stg + SA7 + (uint32_t)((wm * 64 + mt * 16) * A_STR7 + ks * 32) + a_lane);
#pragma unroll
                for (int nt = 0; nt < 8; nt++)
                    mma16816(acc[mt][nt], ah, bh[nt]);
            }
        }
        // no trailing sync: next iteration's sync orders slot reuse
    }

    const int mb = row0 + wm * 64 + (lane >> 2);
    const int nb = col0 + wn * 64 + (lane & 3) * 2;
    if (CH) {
#pragma unroll
        for (int nt = 0; nt < 8; nt++) {
            const int n = nb + nt * 8;
            const float2 bv = *(const float2*)&bias[n];
#pragma unroll
            for (int mt = 0; mt < 4; mt++) {
                const int m = mb + mt * 16;
                if (m < M)
                    *(uint32_t*)&CH[(size_t)m * HID + n] =
                        pk_bf2(__float2bfloat16((acc[mt][nt][0] + bv.x) * oscale),
                               __float2bfloat16((acc[mt][nt][1] + bv.y) * oscale));
                if (m + 8 < M)
                    *(uint32_t*)&CH[(size_t)(m + 8) * HID + n] =
                        pk_bf2(__float2bfloat16((acc[mt][nt][2] + bv.x) * oscale),
                               __float2bfloat16((acc[mt][nt][3] + bv.y) * oscale));
            }
        }
    } else {
#pragma unroll
        for (int nt = 0; nt < 8; nt++) {
            const int n = nb + nt * 8;
            const float2 bv = *(const float2*)&bias[n];
#pragma unroll
            for (int mt = 0; mt < 4; mt++) {
                const int m = mb + mt * 16;
                if (m < M)
                    *(float2*)&Cf[(size_t)m * HID + n] =
                        make_float2(acc[mt][nt][0] + bv.x, acc[mt][nt][1] + bv.y);
                if (m + 8 < M)
                    *(float2*)&Cf[(size_t)(m + 8) * HID + n] =
                        make_float2(acc[mt][nt][2] + bv.x, acc[mt][nt][3] + bv.y);
            }
        }
    }
}

#define CEXP 0.18033688011112042f

__global__ __launch_bounds__(256, 1) void gemm7_qkv_kernel(
    const float* __restrict__ bq, const float* __restrict__ bk, const float* __restrict__ bv) {
    const int z = blockIdx.z;
    const float* bias = (z == 0) ? bq : (z == 1) ? bk : bv;
    __nv_bfloat16* CH = (z == 0) ? g_QH : (z == 1) ? g_KH : g_VH;
    const float sc = (z == 0) ? CEXP : 1.0f;
    gemm7_core(g_augH, g_WH + (size_t)z * WSZ, bias, nullptr, CH, sc, MTOT2);
}

__global__ __launch_bounds__(256, 1) void gemm7_o_kernel(const float* __restrict__ bo) {
    gemm7_core(g_attH, g_WH + 3 * (size_t)WSZ, bo, g_proj, nullptr, 1.0f, MTOT2);
}

// ---------------- attention v11: 3 tiles per barrier (NT=33=3x11), 9-slot ring ----
__device__ __forceinline__ void attn11_load_tile(
    uint32_t slotbase, const __nv_bfloat16* KH, const __nv_bfloat16* VH,
    size_t baseBH, int k0, int tid) {
#pragma unroll
    for (int i = 0; i < 2; i++) {
        int c = tid + i * 256;
        int row = c >> 3, col = c & 7;
        int gr = k0 + row;
        int sz = (gr < SA) ? 16 : 0;
        const __nv_bfloat16* sk = KH + baseBH + (size_t)(sz ? gr : 0) * HID + col * 8;
        const __nv_bfloat16* sv = VH + baseBH + (size_t)(sz ? gr : 0) * HID + col * 8;
        uint32_t off = SWZ((uint32_t)(row * 128 + col * 16));
        cpasync16(slotbase + AT_KH + off, sk, sz);
        cpasync16(slotbase + AT_VH + off, sv, sz);
    }
}
__device__ __forceinline__ void attn11_load_group(
    uint32_t sb, int gslot, const __nv_bfloat16* KH, const __nv_bfloat16* VH,
    size_t baseBH, int k0, int tid) {
#pragma unroll
    for (int t = 0; t < 3; t++)
        attn11_load_tile(sb + (gslot * 3 + t) * AT_STG, KH, VH, baseBH, k0 + t * 64, tid);
}

__global__ __launch_bounds__(256, 1) void attn11_kernel() {
    extern __shared__ char smc[];
    const uint32_t sb = smem_u32(smc);
    const int tid = threadIdx.x, lane = tid & 31, wid = tid >> 5;
    const int qt = blockIdx.x, bh = blockIdx.y, z = blockIdx.z;
    const int b = bh >> 4, h = bh & 15;

    const __nv_bfloat16* QH = g_QH + (size_t)z * STREAM;
    const __nv_bfloat16* KH = g_KH + (size_t)(1 - z) * STREAM;
    const __nv_bfloat16* VH = g_VH + (size_t)(1 - z) * STREAM;
    __nv_bfloat16* OH = g_attH + (size_t)z * STREAM;
    const size_t baseBH = (size_t)b * SA * HID + h * HD;
    const int q0 = qt * 256;

    // ---- stage Q in two 128-row halves; each warp owns 32 q-rows ----
    uint32_t qh[2][4][4];
#pragma unroll 1
    for (int h2 = 0; h2 < 2; h2++) {
        for (int idx = tid; idx < 128 * 8; idx += 256) {
            int r = idx >> 3, c8 = (idx & 7) * 8;
            uint4 hi = make_uint4(0, 0, 0, 0);
            int gr = q0 + h2 * 128 + r;
            if (gr < SA) hi = *(const uint4*)&QH[baseBH + (size_t)gr * HID + c8];
            *(uint4*)(smc + SWZ((uint32_t)(r * 128 + c8 * 2))) = hi;
        }
        __syncthreads();
        if ((wid >> 2) == h2) {
#pragma unroll
            for (int mt = 0; mt < 2; mt++)
#pragma unroll
                for (int ks = 0; ks < 4; ks++) {
                    uint32_t off = SWZ((uint32_t)(((wid & 3) * 32 + mt * 16 + (lane & 15)) * 128
                                                  + ks * 32 + (lane >> 4) * 16));
                    ldmx4(qh[mt][ks], sb + off);
                }
        }
        __syncthreads();
    }

    float o[2][8][4];
#pragma unroll
    for (int m = 0; m < 2; m++)
#pragma unroll
        for (int n = 0; n < 8; n++)
#pragma unroll
            for (int c = 0; c < 4; c++) o[m][n][c] = 0.f;
    float lacc[2][4] = {{0.f, 0.f, 0.f, 0.f}, {0.f, 0.f, 0.f, 0.f}};
    const uint32_t ones_b[2] = {0x3F803F80u, 0x3F803F80u};
    const uint32_t rp = ((lane >> 3) & 1) * 8 + (lane & 7);

    const int NG = 11;   // 33 tiles = 11 groups of 3

    // prologue: groups 0, 1
    attn11_load_group(sb, 0, KH, VH, baseBH, 0, tid);
    cpcommit();
    attn11_load_group(sb, 1, KH, VH, baseBH, 192, tid);
    cpcommit();

    for (int g = 0; g < NG; g++) {
        if (g + 1 < NG) cpwait<1>(); else cpwait<0>();
        __syncthreads();
        // post-sync load of group g+2 into slot (g+2)%3 (read in iter g-1; ordered by sync)
        if (g + 2 < NG) {
            int ns = g + 2; ns -= (ns >= 3 ? 3 : 0); ns -= (ns >= 3 ? 3 : 0);
            int gslot = (g + 2) % 3;
            attn11_load_group(sb, gslot, KH, VH, baseBH, (g + 2) * 192, tid);
            cpcommit();
        }

#pragma unroll
        for (int t = 0; t < 3; t++) {
            const int k0 = g * 192 + t * 64;
            const uint32_t stg = sb + ((g % 3) * 3 + t) * AT_STG;

            // ---- S = Qs @ Kh^T for both subtiles ----
            float s[2][8][4];
#pragma unroll
            for (int m = 0; m < 2; m++)
#pragma unroll
                for (int n = 0; n < 8; n++)
#pragma unroll
                    for (int c = 0; c < 4; c++) s[m][n][c] = 0.f;

#pragma unroll
            for (int kt2 = 0; kt2 < 4; kt2++) {
#pragma unroll
                for (int ks = 0; ks < 4; ks++) {
                    uint32_t off = SWZ((uint32_t)((kt2 * 16 + (lane & 15)) * 128 + ks * 32 + (lane >> 4) * 16));
                    uint32_t kb[4];
                    ldmx4(kb, stg + AT_KH + off);
                    uint32_t blo_h[2] = {kb[0], kb[2]}, bhi_h[2] = {kb[1], kb[3]};
                    mma16816(s[0][2*kt2],     qh[0][ks], blo_h);
                    mma16816(s[0][2*kt2 + 1], qh[0][ks], bhi_h);
                    mma16816(s[1][2*kt2],     qh[1][ks], blo_h);
                    mma16816(s[1][2*kt2 + 1], qh[1][ks], bhi_h);
                }
            }

            // ---- mask edge columns (only final tile: k0=2048) ----
            if (k0 + 64 > SA) {
#pragma unroll
                for (int n = 0; n < 8; n++) {
                    int ktc = k0 + (n >> 1) * 16 + (n & 1) * 8 + (lane & 3) * 2;
#pragma unroll
                    for (int c = 0; c < 4; c++)
                        if (ktc + (c & 1) >= SA) { s[0][n][c] = -2000.f; s[1][n][c] = -2000.f; }
                }
            }

            // ---- p = 2^S via bf16x2 ex2 -> P a-frags; row sums on tensor pipe ----
            uint32_t pa[2][4][4];
#pragma unroll
            for (int m = 0; m < 2; m++)
#pragma unroll
                for (int ks = 0; ks < 4; ks++) {
                    const int j0 = 2 * ks, j1 = 2 * ks + 1;
                    pa[m][ks][0] = ex2_bf2(cvt_bf2(s[m][j0][0], s[m][j0][1]));
                    pa[m][ks][1] = ex2_bf2(cvt_bf2(s[m][j0][2], s[m][j0][3]));
                    pa[m][ks][2] = ex2_bf2(cvt_bf2(s[m][j1][0], s[m][j1][1]));
                    pa[m][ks][3] = ex2_bf2(cvt_bf2(s[m][j1][2], s[m][j1][3]));
                    mma16816(lacc[m], pa[m][ks], ones_b);
                }

            // ---- O += P @ V ----
#pragma unroll
            for (int dt = 0; dt < 4; dt++) {
#pragma unroll
                for (int ks = 0; ks < 4; ks++) {
                    uint32_t off = SWZ((uint32_t)((ks * 16 + rp) * 128 + dt * 32 + (lane >> 4) * 16));
                    uint32_t vb[4];
                    ldmx4t(vb, stg + AT_VH + off);
                    uint32_t b0h[2] = {vb[0], vb[1]}, b1h[2] = {vb[2], vb[3]};
                    mma16816(o[0][2*dt],     pa[0][ks], b0h);
                    mma16816(o[0][2*dt + 1], pa[0][ks], b1h);
                    mma16816(o[1][2*dt],     pa[1][ks], b0h);
                    mma16816(o[1][2*dt + 1], pa[1][ks], b1h);
                }
            }
        }
        // no trailing sync
    }

    // ---- epilogue: normalize, store ----
#pragma unroll
    for (int m = 0; m < 2; m++) {
        const int r0 = q0 + wid * 32 + m * 16 + (lane >> 2);
        const float inv0 = 1.0f / lacc[m][0], inv1 = 1.0f / lacc[m][2];
#pragma unroll
        for (int n = 0; n < 8; n++) {
            const int col = (n >> 1) * 16 + (n & 1) * 8 + (lane & 3) * 2;
            if (r0 < SA)
                *(uint32_t*)&OH[baseBH + (size_t)r0 * HID + col] =
                    pk_bf2(__float2bfloat16(o[m][n][0] * inv0),
                           __float2bfloat16(o[m][n][1] * inv0));
            if (r0 + 8 < SA)
                *(uint32_t*)&OH[baseBH + (size_t)(r0 + 8) * HID + col] =
                    pk_bf2(__float2bfloat16(o[m][n][2] * inv1),
                           __float2bfloat16(o[m][n][3] * inv1));
        }
    }
}

// ---------------- residual (from raw inputs) + LayerNorm + slice -> output -------
__global__ __launch_bounds__(128) void ln_out_kernel(
    const float* __restrict__ cnn, const float* __restrict__ llm,
    const float* __restrict__ gamma, const float* __restrict__ beta,
    float* __restrict__ out) {
    __shared__ float sbuf[4];
    const int row = blockIdx.x;
    const int c = row >> 12;
    const int r = row & 4095;
    const int b = r >> 11;
    const int s = r & 2047;
    const float* resid = (c ? llm : cnn) + ((size_t)(b * SS + s)) * HID;
    const float* proj = g_proj + (size_t)c * STREAM + ((size_t)b * SA + s) * HID;
    const int tid = threadIdx.x;

    float x[8];
    float4 a0 = *(const float4*)&resid[tid * 8];
    float4 a1 = *(const float4*)&resid[tid * 8 + 4];
    float4 p0 = *(const float4*)&proj[tid * 8];
    float4 p1 = *(const float4*)&proj[tid * 8 + 4];
    x[0] = a0.x + p0.x; x[1] = a0.y + p0.y; x[2] = a0.z + p0.z; x[3] = a0.w + p0.w;
    x[4] = a1.x + p1.x; x[5] = a1.y + p1.y; x[6] = a1.z + p1.z; x[7] = a1.w + p1.w;

    float sum = 0.f;
#pragma unroll
    for (int j = 0; j < 8; j++) sum += x[j];
#pragma unroll
    for (int m = 16; m >= 1; m >>= 1) sum += __shfl_xor_sync(0xffffffffu, sum, m);
    if ((tid & 31) == 0) sbuf[tid >> 5] = sum;
    __syncthreads();
    float mu = (sbuf[0] + sbuf[1] + sbuf[2] + sbuf[3]) * (1.0f / HID);
    __syncthreads();

    float vs = 0.f;
#pragma unroll
    for (int j = 0; j < 8; j++) { float d = x[j] - mu; vs += d * d; }
#pragma unroll
    for (int m = 16; m >= 1; m >>= 1) vs += __shfl_xor_sync(0xffffffffu, vs, m);
    if ((tid & 31) == 0) sbuf[tid >> 5] = vs;
    __syncthreads();
    float var = (sbuf[0] + sbuf[1] + sbuf[2] + sbuf[3]) * (1.0f / HID);
    float rstd = rsqrtf(var + 1e-5f);

    float* op = out + (size_t)c * (BB * SS * HID) + ((size_t)b * SS + s) * HID + tid * 8;
    float o[8];
#pragma unroll
    for (int j = 0; j < 8; j++) {
        int col = tid * 8 + j;
        o[j] = (x[j] - mu) * rstd * gamma[col] + beta[col];
    }
    *(float4*)(op)     = make_float4(o[0], o[1], o[2], o[3]);
    *(float4*)(op + 4) = make_float4(o[4], o[5], o[6], o[7]);
}

// ---------------- launch ----------------
extern "C" void kernel_launch(void* const* d_in, const int* in_sizes, int n_in,
                              void* d_out, int out_size) {
    const float* cnn      = (const float*)d_in[0];
    const float* llm      = (const float*)d_in[1];
    const float* Wq       = (const float*)d_in[2];
    const float* bq       = (const float*)d_in[3];
    const float* Wk       = (const float*)d_in[4];
    const float* bk       = (const float*)d_in[5];
    const float* Wv       = (const float*)d_in[6];
    const float* bv       = (const float*)d_in[7];
    const float* Wo       = (const float*)d_in[8];
    const float* bo       = (const float*)d_in[9];
    const float* energy   = (const float*)d_in[10];
    const float* mass     = (const float*)d_in[11];
    const float* momentum = (const float*)d_in[12];
    const float* gamma    = (const float*)d_in[13];
    const float* beta     = (const float*)d_in[14];
    float* out = (float*)d_out;

    const int prep_items = AUG_ITEMS + 4 * W_ITEMS;
    prep_kernel<<<(prep_items + 255) / 256, 256>>>(cnn, llm, energy, mass, momentum,
                                                   Wq, Wk, Wv, Wo);

    cudaFuncSetAttribute(gemm7_qkv_kernel, cudaFuncAttributeMaxDynamicSharedMemorySize, GEMM7_SMEM);
    cudaFuncSetAttribute(gemm7_o_kernel, cudaFuncAttributeMaxDynamicSharedMemorySize, GEMM7_SMEM);
    dim3 ggrid(HID / TN3, (MTOT2 + TM - 1) / TM, 3);   // (4, 65, 3)
    gemm7_qkv_kernel<<<ggrid, 256, GEMM7_SMEM>>>(bq, bk, bv);

    cudaFuncSetAttribute(attn11_kernel, cudaFuncAttributeMaxDynamicSharedMemorySize, ATTN11_SMEM);
    dim3 agrid((SA + 255) / 256, BB * NH, 2);          // (9, 32, 2)
    attn11_kernel<<<agrid, 256, ATTN11_SMEM>>>();

    dim3 ogrid(HID / TN3, (MTOT2 + TM - 1) / TM, 1);   // (4, 65)
    gemm7_o_kernel<<<ogrid, 256, GEMM7_SMEM>>>(bo);

    ln_out_kernel<<<2 * BB * SS, 128>>>(cnn, llm, gamma, beta, out);
}